// round 4
// baseline (speedup 1.0000x reference)
#include <cuda_runtime.h>
#include <cstdint>
#include <cstddef>

// ---------------------------------------------------------------------------
// GlobalFeatureMoE: AdaLN + top-2 MoE (8 routed + 1 shared expert) + residual
// T=8192 tokens, D=1024, H=HS=4096, E=8, K=2
// Strategy: fp32 gate (exact routing), tf32 mma.sync GEMMs (sparse dispatch)
// ---------------------------------------------------------------------------

constexpr int TKN  = 8192;   // B*L
constexpr int DIM  = 1024;
constexpr int NEXP = 8;
constexpr int HID  = 4096;
constexpr int NBATCH = 4;
constexpr int SEQ  = 2048;

// scratch (static __device__ arrays — allocation-free per harness rules)
__device__ float g_xn[(size_t)TKN * DIM];          // 32 MB  normalized tokens
__device__ float g_cond[NBATCH * 2 * DIM];         // shift/scale per batch
__device__ int   g_cnt[NEXP];                      // tokens per routed expert
__device__ int   g_idx[NEXP * TKN];                // bucket slot -> token id
__device__ int   g_re[2 * TKN];                    // token -> expert ids
__device__ int   g_rs[2 * TKN];                    // token -> bucket slots
__device__ float g_rw[2 * TKN];                    // token -> combine weights
__device__ float g_h [(size_t)9 * TKN * HID];      // 1.2 GB  hidden per bucket
__device__ float g_o2[(size_t)9 * TKN * DIM];      // 302 MB  expert outputs

// ---------------------------------------------------------------------------
__global__ void init_kernel() {
    if (threadIdx.x < NEXP) g_cnt[threadIdx.x] = 0;
}

// cond = silu(time_c) @ ada_w + ada_b   -> (B, 2D)
__global__ void cond_kernel(const float* __restrict__ tc,
                            const float* __restrict__ aw,
                            const float* __restrict__ ab) {
    __shared__ float s[DIM];
    int b = blockIdx.y;
    for (int i = threadIdx.x; i < DIM; i += blockDim.x) {
        float v = tc[(size_t)b * DIM + i];
        s[i] = v / (1.0f + expf(-v));
    }
    __syncthreads();
    int col = blockIdx.x * blockDim.x + threadIdx.x;   // 0..2047
    float acc = ab[col];
    #pragma unroll 8
    for (int k = 0; k < DIM; ++k)
        acc += s[k] * aw[(size_t)k * (2 * DIM) + col];
    g_cond[(size_t)b * (2 * DIM) + col] = acc;
}

// fused AdaLN + fp32 gate + top-2 routing.  one block (256 thr) per token.
__global__ void adaln_route(const float* __restrict__ x,
                            const float* __restrict__ gw) {
    int t   = blockIdx.x;
    int tid = threadIdx.x;
    int lane = tid & 31, wid = tid >> 5;
    int b = t / SEQ;

    float4 xv = reinterpret_cast<const float4*>(x + (size_t)t * DIM)[tid];
    float s  = xv.x + xv.y + xv.z + xv.w;
    float ss = xv.x*xv.x + xv.y*xv.y + xv.z*xv.z + xv.w*xv.w;
    #pragma unroll
    for (int o = 16; o > 0; o >>= 1) {
        s  += __shfl_down_sync(0xffffffffu, s,  o);
        ss += __shfl_down_sync(0xffffffffu, ss, o);
    }
    __shared__ float red[2][8];
    if (lane == 0) { red[0][wid] = s; red[1][wid] = ss; }
    __syncthreads();
    float mu = 0.f, m2 = 0.f;
    #pragma unroll
    for (int w = 0; w < 8; ++w) { mu += red[0][w]; m2 += red[1][w]; }
    mu *= (1.0f / DIM); m2 *= (1.0f / DIM);
    float rstd = rsqrtf(m2 - mu * mu + 1e-6f);

    float4 sh = reinterpret_cast<const float4*>(g_cond + (size_t)b*2*DIM)[tid];
    float4 sc = reinterpret_cast<const float4*>(g_cond + (size_t)b*2*DIM + DIM)[tid];
    float4 xn;
    xn.x = (xv.x - mu) * rstd * (1.0f + sc.x) + sh.x;
    xn.y = (xv.y - mu) * rstd * (1.0f + sc.y) + sh.y;
    xn.z = (xv.z - mu) * rstd * (1.0f + sc.z) + sh.z;
    xn.w = (xv.w - mu) * rstd * (1.0f + sc.w) + sh.w;
    reinterpret_cast<float4*>(g_xn + (size_t)t * DIM)[tid] = xn;

    // gate logits in exact fp32
    float l[8];
    #pragma unroll
    for (int e = 0; e < 8; ++e) l[e] = 0.f;
    int d = tid * 4;
    float xs[4] = {xn.x, xn.y, xn.z, xn.w};
    #pragma unroll
    for (int j = 0; j < 4; ++j) {
        const float* wr = gw + (size_t)(d + j) * NEXP;
        #pragma unroll
        for (int e = 0; e < 8; ++e) l[e] += xs[j] * wr[e];
    }
    #pragma unroll
    for (int e = 0; e < 8; ++e) {
        #pragma unroll
        for (int o = 16; o > 0; o >>= 1)
            l[e] += __shfl_down_sync(0xffffffffu, l[e], o);
    }
    __shared__ float lred[8][8];
    if (lane == 0) {
        #pragma unroll
        for (int e = 0; e < 8; ++e) lred[e][wid] = l[e];
    }
    __syncthreads();
    if (tid == 0) {
        float L[8];
        #pragma unroll
        for (int e = 0; e < 8; ++e) {
            float a = 0.f;
            for (int w = 0; w < 8; ++w) a += lred[e][w];
            L[e] = a;
        }
        float mx = L[0];
        for (int e = 1; e < 8; ++e) mx = fmaxf(mx, L[e]);
        float p[8];
        for (int e = 0; e < 8; ++e) p[e] = expf(L[e] - mx);
        // top-2, ties -> lower index (matches lax.top_k)
        int ia = 0; float va = p[0];
        for (int e = 1; e < 8; ++e) if (p[e] > va) { ia = e; va = p[e]; }
        int ib = -1; float vb = -1.f;
        for (int e = 0; e < 8; ++e) if (e != ia && p[e] > vb) { ib = e; vb = p[e]; }
        float inv = 1.0f / (va + vb);
        int sa = atomicAdd(&g_cnt[ia], 1);
        int sb = atomicAdd(&g_cnt[ib], 1);
        g_idx[ia * TKN + sa] = t;
        g_idx[ib * TKN + sb] = t;
        g_re[2*t]   = ia; g_rs[2*t]   = sa; g_rw[2*t]   = va * inv;
        g_re[2*t+1] = ib; g_rs[2*t+1] = sb; g_rw[2*t+1] = vb * inv;
    }
}

// ---------------------------------------------------------------------------
// tf32 tensor-core GEMM, 128x128x16 block tile, 8 warps (32x64 each),
// double-buffered smem.  blockIdx.z = expert (0..7 routed, 8 = shared).
// ---------------------------------------------------------------------------
__device__ __forceinline__ float tf32r(float f) {
    unsigned u;
    asm("cvt.rna.tf32.f32 %0, %1;" : "=r"(u) : "f"(f));
    return __uint_as_float(u);
}
__device__ __forceinline__ float gelu_t(float v) {
    float u = 0.7978845608028654f * (v + 0.044715f * v * v * v);
    return 0.5f * v * (1.0f + tanhf(u));
}
__device__ __forceinline__ void mma_tf32(float* c, const unsigned* a, const unsigned* b) {
    asm volatile(
        "mma.sync.aligned.m16n8k8.row.col.f32.tf32.tf32.f32 "
        "{%0,%1,%2,%3}, {%4,%5,%6,%7}, {%8,%9}, {%0,%1,%2,%3};\n"
        : "+f"(c[0]), "+f"(c[1]), "+f"(c[2]), "+f"(c[3])
        : "r"(a[0]), "r"(a[1]), "r"(a[2]), "r"(a[3]), "r"(b[0]), "r"(b[1]));
}

template <bool GATHER>   // GATHER=true: xn -> gelu(xW1+b1)=h ; false: h -> hW2+b2
__global__ __launch_bounds__(256) void gemm_tf32_k(
    const float* __restrict__ Wr, const float* __restrict__ Ws,
    const float* __restrict__ br, const float* __restrict__ bs) {
    constexpr int N   = GATHER ? HID : DIM;
    constexpr int KD  = GATHER ? DIM : HID;
    constexpr int LDA = GATHER ? DIM : HID;

    __shared__ float As[2][128][20];
    __shared__ float Bs[2][16][136];
    __shared__ int   rIdx[128];

    const int e   = blockIdx.z;
    const int cnt = (e < NEXP) ? g_cnt[e] : TKN;
    const int m0  = blockIdx.y * 128;
    if (m0 >= cnt) return;
    const int n0  = blockIdx.x * 128;
    const float* W    = (e < NEXP) ? Wr + (size_t)e * KD * N : Ws;
    const float* bias = (e < NEXP) ? br + (size_t)e * N      : bs;
    const float* A = GATHER ? g_xn : g_h;
    float*       Out = GATHER ? g_h : g_o2;

    const int tid = threadIdx.x;
    if (tid < 128) {
        int r = m0 + tid;
        int idx;
        if (GATHER) idx = (e < NEXP) ? ((r < cnt) ? g_idx[e * TKN + r] : 0) : r;
        else        idx = e * TKN + r;
        rIdx[tid] = idx;
    }
    __syncthreads();

    const int ar   = tid >> 2;
    const int ac   = (tid & 3) * 4;
    const int brow = tid >> 5;
    const int bc   = (tid & 31) * 4;
    const float* Ap0 = A + (size_t)rIdx[ar]      * LDA + ac;
    const float* Ap1 = A + (size_t)rIdx[ar + 64] * LDA + ac;
    const float* Bp0 = W + (size_t)brow       * N + n0 + bc;
    const float* Bp1 = W + (size_t)(brow + 8) * N + n0 + bc;

    float acc[2][8][4];
    #pragma unroll
    for (int i = 0; i < 2; ++i)
        #pragma unroll
        for (int j = 0; j < 8; ++j)
            #pragma unroll
            for (int k = 0; k < 4; ++k) acc[i][j][k] = 0.f;

    const int lane = tid & 31;
    const int wm = (tid >> 5) >> 1;   // 0..3
    const int wn = (tid >> 5) & 1;    // 0..1
    const int grp = lane >> 2;
    const int qid = lane & 3;

    auto stage = [&](int bi, float4 a0, float4 a1, float4 b0, float4 b1) {
        As[bi][ar][ac+0]    = tf32r(a0.x); As[bi][ar][ac+1]    = tf32r(a0.y);
        As[bi][ar][ac+2]    = tf32r(a0.z); As[bi][ar][ac+3]    = tf32r(a0.w);
        As[bi][ar+64][ac+0] = tf32r(a1.x); As[bi][ar+64][ac+1] = tf32r(a1.y);
        As[bi][ar+64][ac+2] = tf32r(a1.z); As[bi][ar+64][ac+3] = tf32r(a1.w);
        Bs[bi][brow][bc+0]   = tf32r(b0.x); Bs[bi][brow][bc+1]   = tf32r(b0.y);
        Bs[bi][brow][bc+2]   = tf32r(b0.z); Bs[bi][brow][bc+3]   = tf32r(b0.w);
        Bs[bi][brow+8][bc+0] = tf32r(b1.x); Bs[bi][brow+8][bc+1] = tf32r(b1.y);
        Bs[bi][brow+8][bc+2] = tf32r(b1.z); Bs[bi][brow+8][bc+3] = tf32r(b1.w);
    };

    {
        float4 a0 = *(const float4*)Ap0;
        float4 a1 = *(const float4*)Ap1;
        float4 b0 = *(const float4*)Bp0;
        float4 b1 = *(const float4*)Bp1;
        stage(0, a0, a1, b0, b1);
    }
    __syncthreads();

    constexpr int NK = KD / 16;
    int buf = 0;
    for (int kt = 0; kt < NK; ++kt) {
        float4 a0, a1, b0, b1;
        const bool more = (kt + 1 < NK);
        if (more) {
            int k = (kt + 1) * 16;
            a0 = *(const float4*)(Ap0 + k);
            a1 = *(const float4*)(Ap1 + k);
            b0 = *(const float4*)(Bp0 + (size_t)k * N);
            b1 = *(const float4*)(Bp1 + (size_t)k * N);
        }
        #pragma unroll
        for (int ks = 0; ks < 16; ks += 8) {
            unsigned af[2][4], bf[8][2];
            #pragma unroll
            for (int mi = 0; mi < 2; ++mi) {
                int r0 = wm * 32 + mi * 16 + grp;
                af[mi][0] = __float_as_uint(As[buf][r0][ks + qid]);
                af[mi][1] = __float_as_uint(As[buf][r0 + 8][ks + qid]);
                af[mi][2] = __float_as_uint(As[buf][r0][ks + qid + 4]);
                af[mi][3] = __float_as_uint(As[buf][r0 + 8][ks + qid + 4]);
            }
            #pragma unroll
            for (int ni = 0; ni < 8; ++ni) {
                int c = wn * 64 + ni * 8 + grp;
                bf[ni][0] = __float_as_uint(Bs[buf][ks + qid][c]);
                bf[ni][1] = __float_as_uint(Bs[buf][ks + qid + 4][c]);
            }
            #pragma unroll
            for (int mi = 0; mi < 2; ++mi)
                #pragma unroll
                for (int ni = 0; ni < 8; ++ni)
                    mma_tf32(acc[mi][ni], af[mi], bf[ni]);
        }
        if (more) stage(buf ^ 1, a0, a1, b0, b1);
        __syncthreads();
        buf ^= 1;
    }

    // epilogue
    const size_t ob = (size_t)e * TKN * N;
    #pragma unroll
    for (int mi = 0; mi < 2; ++mi) {
        int r0 = m0 + wm * 32 + mi * 16 + grp;
        #pragma unroll
        for (int ni = 0; ni < 8; ++ni) {
            int c = n0 + wn * 64 + ni * 8 + qid * 2;
            float bv0 = bias[c], bv1 = bias[c + 1];
            float v00 = acc[mi][ni][0] + bv0;
            float v01 = acc[mi][ni][1] + bv1;
            float v10 = acc[mi][ni][2] + bv0;
            float v11 = acc[mi][ni][3] + bv1;
            if (GATHER) {
                v00 = gelu_t(v00); v01 = gelu_t(v01);
                v10 = gelu_t(v10); v11 = gelu_t(v11);
            }
            if (r0 < cnt) {
                Out[ob + (size_t)r0 * N + c]     = v00;
                Out[ob + (size_t)r0 * N + c + 1] = v01;
            }
            if (r0 + 8 < cnt) {
                Out[ob + (size_t)(r0 + 8) * N + c]     = v10;
                Out[ob + (size_t)(r0 + 8) * N + c + 1] = v11;
            }
        }
    }
}

// out = x + shared + w0*routed0 + w1*routed1
__global__ void combine_kernel(const float* __restrict__ x, float* __restrict__ out) {
    int t = blockIdx.x, tid = threadIdx.x;
    int e0 = g_re[2*t],     s0 = g_rs[2*t];
    int e1 = g_re[2*t + 1], s1 = g_rs[2*t + 1];
    float w0 = g_rw[2*t], w1 = g_rw[2*t + 1];
    const float4* xp  = (const float4*)(x + (size_t)t * DIM);
    const float4* shp = (const float4*)(g_o2 + ((size_t)NEXP * TKN + t) * DIM);
    const float4* r0p = (const float4*)(g_o2 + ((size_t)e0 * TKN + s0) * DIM);
    const float4* r1p = (const float4*)(g_o2 + ((size_t)e1 * TKN + s1) * DIM);
    float4 xv = xp[tid], sv = shp[tid], a = r0p[tid], b = r1p[tid];
    float4 o;
    o.x = xv.x + sv.x + w0 * a.x + w1 * b.x;
    o.y = xv.y + sv.y + w0 * a.y + w1 * b.y;
    o.z = xv.z + sv.z + w0 * a.z + w1 * b.z;
    o.w = xv.w + sv.w + w0 * a.w + w1 * b.w;
    ((float4*)(out + (size_t)t * DIM))[tid] = o;
}

// ---------------------------------------------------------------------------
extern "C" void kernel_launch(void* const* d_in, const int* in_sizes, int n_in,
                              void* d_out, int out_size) {
    const float* x   = (const float*)d_in[0];
    const float* tc  = (const float*)d_in[1];
    const float* aw  = (const float*)d_in[2];
    const float* ab  = (const float*)d_in[3];
    const float* gw  = (const float*)d_in[4];
    const float* w1  = (const float*)d_in[5];
    const float* b1  = (const float*)d_in[6];
    const float* w2  = (const float*)d_in[7];
    const float* b2  = (const float*)d_in[8];
    const float* sw1 = (const float*)d_in[9];
    const float* sb1 = (const float*)d_in[10];
    const float* sw2 = (const float*)d_in[11];
    const float* sb2 = (const float*)d_in[12];
    float* out = (float*)d_out;

    init_kernel<<<1, 32>>>();
    cond_kernel<<<dim3((2 * DIM) / 256, NBATCH), 256>>>(tc, aw, ab);
    adaln_route<<<TKN, 256>>>(x, gw);
    gemm_tf32_k<true ><<<dim3(HID / 128, TKN / 128, 9), 256>>>(w1, sw1, b1, sb1);
    gemm_tf32_k<false><<<dim3(DIM / 128, TKN / 128, 9), 256>>>(w2, sw2, b2, sb2);
    combine_kernel<<<TKN, 256>>>(x, out);
}

// round 6
// speedup vs baseline: 1.4009x; 1.4009x over previous
#include <cuda_runtime.h>
#include <cuda_fp16.h>
#include <cstdint>
#include <cstddef>

// ---------------------------------------------------------------------------
// GlobalFeatureMoE: AdaLN + top-2 MoE (8 routed + 1 shared expert) + residual
// fp16 mma.sync.m16n8k16 GEMMs (fp32 accum), ldmatrix fragments, cp.async
// 4-stage pipeline.  fp32 gate for exact routing.
// ---------------------------------------------------------------------------

constexpr int TKN  = 8192;   // B*L
constexpr int DIM  = 1024;
constexpr int NEXP = 8;
constexpr int HID  = 4096;
constexpr int NBATCH = 4;
constexpr int SEQ  = 2048;

constexpr int BM = 256, BN = 128, BK = 32, NSTAGE = 4;
constexpr int STAGE = 24576;               // A 16KB (2 x 8KB k16-blocks) + B 8KB
constexpr int SMEM_BYTES = NSTAGE * STAGE; // 98304

// scratch (static __device__ arrays — allocation-free per harness rules)
__device__ float  g_cond[NBATCH * 2 * DIM];
__device__ int    g_cnt[NEXP];
__device__ int    g_idx[NEXP * TKN];
__device__ int    g_re[2 * TKN];
__device__ int    g_rs[2 * TKN];
__device__ float  g_rw[2 * TKN];
__device__ __half g_xnh[(size_t)TKN * DIM];          // fp16 normalized tokens
__device__ __half g_hf [(size_t)9 * TKN * HID];      // fp16 hidden per bucket
__device__ float  g_o2 [(size_t)9 * TKN * DIM];      // fp32 expert outputs
__device__ __half g_w1h[(size_t)NEXP * DIM * HID];
__device__ __half g_w2h[(size_t)NEXP * HID * DIM];
__device__ __half g_sw1h[(size_t)DIM * HID];
__device__ __half g_sw2h[(size_t)HID * DIM];

// ---------------------------------------------------------------------------
__device__ __forceinline__ uint32_t smem_u32(const void* p) {
    uint32_t a;
    asm("{ .reg .u64 t; cvta.to.shared.u64 t, %1; cvt.u32.u64 %0, t; }" : "=r"(a) : "l"(p));
    return a;
}
#define CP_ASYNC16(dst, src) \
    asm volatile("cp.async.cg.shared.global [%0], [%1], 16;" :: "r"(dst), "l"(src))
#define CP_COMMIT() asm volatile("cp.async.commit_group;" ::: "memory")
#define CP_WAIT(n)  asm volatile("cp.async.wait_group %0;" :: "n"(n) : "memory")

#define LDSM_X4(r, addr) \
    asm volatile("ldmatrix.sync.aligned.m8n8.x4.shared.b16 {%0,%1,%2,%3}, [%4];" \
        : "=r"((r)[0]), "=r"((r)[1]), "=r"((r)[2]), "=r"((r)[3]) : "r"(addr))
#define LDSM_X4T(r, addr) \
    asm volatile("ldmatrix.sync.aligned.m8n8.x4.trans.shared.b16 {%0,%1,%2,%3}, [%4];" \
        : "=r"((r)[0]), "=r"((r)[1]), "=r"((r)[2]), "=r"((r)[3]) : "r"(addr))

__device__ __forceinline__ void mma_f16(float* c, const uint32_t* a, const uint32_t* b) {
    asm volatile(
        "mma.sync.aligned.m16n8k16.row.col.f32.f16.f16.f32 "
        "{%0,%1,%2,%3}, {%4,%5,%6,%7}, {%8,%9}, {%0,%1,%2,%3};\n"
        : "+f"(c[0]), "+f"(c[1]), "+f"(c[2]), "+f"(c[3])
        : "r"(a[0]), "r"(a[1]), "r"(a[2]), "r"(a[3]), "r"(b[0]), "r"(b[1]));
}

__device__ __forceinline__ float gelu_t(float v) {
    float u = 0.7978845608028654f * (v + 0.044715f * v * v * v);
    return 0.5f * v * (1.0f + tanhf(u));
}

// ---------------------------------------------------------------------------
__global__ void init_kernel() {
    if (threadIdx.x < NEXP) g_cnt[threadIdx.x] = 0;
}

// fp32 -> fp16 bulk convert (weights)
__global__ void f2h_kernel(const float4* __restrict__ in, uint2* __restrict__ out, int n4) {
    int i = blockIdx.x * blockDim.x + threadIdx.x;
    if (i < n4) {
        float4 v = in[i];
        __half2 a = __floats2half2_rn(v.x, v.y);
        __half2 b = __floats2half2_rn(v.z, v.w);
        out[i] = make_uint2(*(uint32_t*)&a, *(uint32_t*)&b);
    }
}

// cond = silu(time_c) @ ada_w + ada_b
__global__ void cond_kernel(const float* __restrict__ tc,
                            const float* __restrict__ aw,
                            const float* __restrict__ ab) {
    __shared__ float s[DIM];
    int b = blockIdx.y;
    for (int i = threadIdx.x; i < DIM; i += blockDim.x) {
        float v = tc[(size_t)b * DIM + i];
        s[i] = v / (1.0f + expf(-v));
    }
    __syncthreads();
    int col = blockIdx.x * blockDim.x + threadIdx.x;
    float acc = ab[col];
    #pragma unroll 8
    for (int k = 0; k < DIM; ++k)
        acc += s[k] * aw[(size_t)k * (2 * DIM) + col];
    g_cond[(size_t)b * (2 * DIM) + col] = acc;
}

// fused AdaLN + fp32 gate + top-2 routing; writes fp16 xn
__global__ void adaln_route(const float* __restrict__ x,
                            const float* __restrict__ gw) {
    int t   = blockIdx.x;
    int tid = threadIdx.x;
    int lane = tid & 31, wid = tid >> 5;
    int b = t / SEQ;

    float4 xv = reinterpret_cast<const float4*>(x + (size_t)t * DIM)[tid];
    float s  = xv.x + xv.y + xv.z + xv.w;
    float ss = xv.x*xv.x + xv.y*xv.y + xv.z*xv.z + xv.w*xv.w;
    #pragma unroll
    for (int o = 16; o > 0; o >>= 1) {
        s  += __shfl_down_sync(0xffffffffu, s,  o);
        ss += __shfl_down_sync(0xffffffffu, ss, o);
    }
    __shared__ float red[2][8];
    if (lane == 0) { red[0][wid] = s; red[1][wid] = ss; }
    __syncthreads();
    float mu = 0.f, m2 = 0.f;
    #pragma unroll
    for (int w = 0; w < 8; ++w) { mu += red[0][w]; m2 += red[1][w]; }
    mu *= (1.0f / DIM); m2 *= (1.0f / DIM);
    float rstd = rsqrtf(m2 - mu * mu + 1e-6f);

    float4 sh = reinterpret_cast<const float4*>(g_cond + (size_t)b*2*DIM)[tid];
    float4 sc = reinterpret_cast<const float4*>(g_cond + (size_t)b*2*DIM + DIM)[tid];
    float4 xn;
    xn.x = (xv.x - mu) * rstd * (1.0f + sc.x) + sh.x;
    xn.y = (xv.y - mu) * rstd * (1.0f + sc.y) + sh.y;
    xn.z = (xv.z - mu) * rstd * (1.0f + sc.z) + sh.z;
    xn.w = (xv.w - mu) * rstd * (1.0f + sc.w) + sh.w;
    {
        __half2 h01 = __floats2half2_rn(xn.x, xn.y);
        __half2 h23 = __floats2half2_rn(xn.z, xn.w);
        *(uint2*)(g_xnh + (size_t)t * DIM + tid * 4) =
            make_uint2(*(uint32_t*)&h01, *(uint32_t*)&h23);
    }

    // gate logits in exact fp32
    float l[8];
    #pragma unroll
    for (int e = 0; e < 8; ++e) l[e] = 0.f;
    int d = tid * 4;
    float xs[4] = {xn.x, xn.y, xn.z, xn.w};
    #pragma unroll
    for (int j = 0; j < 4; ++j) {
        const float* wr = gw + (size_t)(d + j) * NEXP;
        #pragma unroll
        for (int e = 0; e < 8; ++e) l[e] += xs[j] * wr[e];
    }
    #pragma unroll
    for (int e = 0; e < 8; ++e) {
        #pragma unroll
        for (int o = 16; o > 0; o >>= 1)
            l[e] += __shfl_down_sync(0xffffffffu, l[e], o);
    }
    __shared__ float lred[8][8];
    if (lane == 0) {
        #pragma unroll
        for (int e = 0; e < 8; ++e) lred[e][wid] = l[e];
    }
    __syncthreads();
    if (tid == 0) {
        float L[8];
        #pragma unroll
        for (int e = 0; e < 8; ++e) {
            float a = 0.f;
            for (int w = 0; w < 8; ++w) a += lred[e][w];
            L[e] = a;
        }
        float mx = L[0];
        for (int e = 1; e < 8; ++e) mx = fmaxf(mx, L[e]);
        float p[8];
        for (int e = 0; e < 8; ++e) p[e] = expf(L[e] - mx);
        int ia = 0; float va = p[0];
        for (int e = 1; e < 8; ++e) if (p[e] > va) { ia = e; va = p[e]; }
        int ib = -1; float vb = -1.f;
        for (int e = 0; e < 8; ++e) if (e != ia && p[e] > vb) { ib = e; vb = p[e]; }
        float inv = 1.0f / (va + vb);
        int sa = atomicAdd(&g_cnt[ia], 1);
        int sb = atomicAdd(&g_cnt[ib], 1);
        g_idx[ia * TKN + sa] = t;
        g_idx[ib * TKN + sb] = t;
        g_re[2*t]   = ia; g_rs[2*t]   = sa; g_rw[2*t]   = va * inv;
        g_re[2*t+1] = ib; g_rs[2*t+1] = sb; g_rw[2*t+1] = vb * inv;
    }
}

// ---------------------------------------------------------------------------
// fp16 GEMM: CTA 256x128xBK32, 8 warps (4m x 2n) of 64x64, 4-stage cp.async.
// A smem: per k16-block [256 rows][32B], granule c at +((c ^ ((m>>2)&1))<<4)
// B smem: [32 k][256B], granule gn at +(((gn ^ (k&7)))<<4)
// blockIdx.z = expert (0..7 routed, 8 = shared)
// ---------------------------------------------------------------------------
template <bool GATHER>   // true: xnh -> gelu(xW1+b1) = g_hf ; false: g_hf -> hW2+b2 = g_o2
__global__ __launch_bounds__(256, 1) void moe_hgemm(
    const __half* __restrict__ Wr, const __half* __restrict__ Ws,
    const float* __restrict__ br, const float* __restrict__ bs) {
    constexpr int NOUT = GATHER ? HID : DIM;
    constexpr int KD   = GATHER ? DIM : HID;
    constexpr int NKT  = KD / BK;

    extern __shared__ char smem[];
    const int e   = blockIdx.z;
    const int cnt = (e < NEXP) ? g_cnt[e] : TKN;
    const int m0  = blockIdx.y * BM;
    if (m0 >= cnt) return;
    const int n0  = blockIdx.x * BN;
    const __half* W    = (e < NEXP) ? Wr + (size_t)e * KD * NOUT : Ws;
    const float*  bias = (e < NEXP) ? br + (size_t)e * NOUT      : bs;
    const __half* Ah   = GATHER ? g_xnh : g_hf;

    const uint32_t sbase = smem_u32(smem);
    const int tid = threadIdx.x, lane = tid & 31, wid = tid >> 5;
    const int wm = wid >> 1, wn = wid & 1;

    // ---- staging assignment: A row 'tid' (4 chunks), B chunks 2*tid, 2*tid+1
    int gr_s = m0 + tid;
    long aidx;
    if (GATHER) aidx = (e < NEXP) ? ((gr_s < cnt) ? g_idx[e * TKN + gr_s] : 0) : gr_s;
    else        aidx = (long)e * TKN + gr_s;
    const char* aRow = (const char*)(Ah + (size_t)aidx * KD);
    uint32_t aOff[4];
    #pragma unroll
    for (int s2 = 0; s2 < 2; ++s2)
        #pragma unroll
        for (int c = 0; c < 2; ++c)
            aOff[s2 * 2 + c] = (uint32_t)(s2 * 8192 + tid * 32 + ((c ^ ((tid >> 2) & 1)) << 4));
    const int bk0 = tid >> 3;                 // 0..31
    const int gn0 = (tid * 2) & 15;           // even
    const char* bRow = (const char*)(W + (size_t)bk0 * NOUT + n0 + gn0 * 8);
    uint32_t bOff[2];
    #pragma unroll
    for (int c = 0; c < 2; ++c)
        bOff[c] = (uint32_t)(16384 + bk0 * 256 + (((gn0 + c) ^ (bk0 & 7)) << 4));
    const size_t bStride = (size_t)BK * NOUT * sizeof(__half);   // per-stage k advance

    auto load_stage = [&](int kt) {
        uint32_t so = sbase + (uint32_t)((kt & (NSTAGE - 1)) * STAGE);
        const char* as = aRow + (size_t)kt * (BK * 2);
        CP_ASYNC16(so + aOff[0], as + 0);
        CP_ASYNC16(so + aOff[1], as + 16);
        CP_ASYNC16(so + aOff[2], as + 32);
        CP_ASYNC16(so + aOff[3], as + 48);
        const char* bsrc = bRow + (size_t)kt * bStride;
        CP_ASYNC16(so + bOff[0], bsrc);
        CP_ASYNC16(so + bOff[1], bsrc + 16);
        CP_COMMIT();
    };

    // ---- fragment addresses (per lane, stage-relative)
    const int rr = lane & 15, cc = lane >> 4;
    const uint32_t aswz = (uint32_t)((cc ^ ((rr >> 2) & 1)) << 4);
    uint32_t aAddr[4];
    #pragma unroll
    for (int mi = 0; mi < 4; ++mi)
        aAddr[mi] = (uint32_t)((wm * 64 + mi * 16 + rr) * 32) + aswz;
    const int kk = ((lane >> 3) & 1) * 8 + (lane & 7);
    const int j2 = lane >> 4;
    uint32_t bAddr[4];
    #pragma unroll
    for (int p = 0; p < 4; ++p)
        bAddr[p] = (uint32_t)(16384 + kk * 256 + (((wn * 8 + p * 2 + j2) ^ (lane & 7)) << 4));

    float acc[4][8][4];
    #pragma unroll
    for (int mi = 0; mi < 4; ++mi)
        #pragma unroll
        for (int ni = 0; ni < 8; ++ni)
            #pragma unroll
            for (int q = 0; q < 4; ++q) acc[mi][ni][q] = 0.f;

    load_stage(0); load_stage(1); load_stage(2);

    for (int kt = 0; kt < NKT; ++kt) {
        CP_WAIT(2);
        __syncthreads();
        if (kt + 3 < NKT) load_stage(kt + 3); else CP_COMMIT();

        const uint32_t sA = sbase + (uint32_t)((kt & (NSTAGE - 1)) * STAGE);
        #pragma unroll
        for (int s2 = 0; s2 < 2; ++s2) {
            uint32_t a[4][4], b[8][2];
            #pragma unroll
            for (int mi = 0; mi < 4; ++mi)
                LDSM_X4(a[mi], sA + s2 * 8192 + aAddr[mi]);
            #pragma unroll
            for (int p = 0; p < 4; ++p) {
                uint32_t t4[4];
                LDSM_X4T(t4, sA + s2 * 4096 + bAddr[p]);
                b[2*p][0] = t4[0]; b[2*p][1] = t4[1];
                b[2*p+1][0] = t4[2]; b[2*p+1][1] = t4[3];
            }
            #pragma unroll
            for (int mi = 0; mi < 4; ++mi)
                #pragma unroll
                for (int ni = 0; ni < 8; ++ni)
                    mma_f16(acc[mi][ni], a[mi], b[ni]);
        }
    }

    // ---- epilogue
    const int grp = lane >> 2, qid = lane & 3;
    #pragma unroll
    for (int mi = 0; mi < 4; ++mi) {
        const int r0 = m0 + wm * 64 + mi * 16 + grp;
        #pragma unroll
        for (int ni = 0; ni < 8; ++ni) {
            const int c = n0 + wn * 64 + ni * 8 + qid * 2;
            const float2 bv = *(const float2*)(bias + c);
            float v00 = acc[mi][ni][0] + bv.x;
            float v01 = acc[mi][ni][1] + bv.y;
            float v10 = acc[mi][ni][2] + bv.x;
            float v11 = acc[mi][ni][3] + bv.y;
            if (GATHER) {
                v00 = gelu_t(v00); v01 = gelu_t(v01);
                v10 = gelu_t(v10); v11 = gelu_t(v11);
                if (r0 < cnt) {
                    __half2 h = __floats2half2_rn(v00, v01);
                    *(__half2*)(g_hf + ((size_t)e * TKN + r0) * NOUT + c) = h;
                }
                if (r0 + 8 < cnt) {
                    __half2 h = __floats2half2_rn(v10, v11);
                    *(__half2*)(g_hf + ((size_t)e * TKN + r0 + 8) * NOUT + c) = h;
                }
            } else {
                if (r0 < cnt)
                    *(float2*)(g_o2 + ((size_t)e * TKN + r0) * NOUT + c) = make_float2(v00, v01);
                if (r0 + 8 < cnt)
                    *(float2*)(g_o2 + ((size_t)e * TKN + r0 + 8) * NOUT + c) = make_float2(v10, v11);
            }
        }
    }
}

// out = x + shared + w0*routed0 + w1*routed1
__global__ void combine_kernel(const float* __restrict__ x, float* __restrict__ out) {
    int t = blockIdx.x, tid = threadIdx.x;
    int e0 = g_re[2*t],     s0 = g_rs[2*t];
    int e1 = g_re[2*t + 1], s1 = g_rs[2*t + 1];
    float w0 = g_rw[2*t], w1 = g_rw[2*t + 1];
    const float4* xp  = (const float4*)(x + (size_t)t * DIM);
    const float4* shp = (const float4*)(g_o2 + ((size_t)NEXP * TKN + t) * DIM);
    const float4* r0p = (const float4*)(g_o2 + ((size_t)e0 * TKN + s0) * DIM);
    const float4* r1p = (const float4*)(g_o2 + ((size_t)e1 * TKN + s1) * DIM);
    float4 xv = xp[tid], sv = shp[tid], a = r0p[tid], b = r1p[tid];
    float4 o;
    o.x = xv.x + sv.x + w0 * a.x + w1 * b.x;
    o.y = xv.y + sv.y + w0 * a.y + w1 * b.y;
    o.z = xv.z + sv.z + w0 * a.z + w1 * b.z;
    o.w = xv.w + sv.w + w0 * a.w + w1 * b.w;
    ((float4*)(out + (size_t)t * DIM))[tid] = o;
}

// ---------------------------------------------------------------------------
extern "C" void kernel_launch(void* const* d_in, const int* in_sizes, int n_in,
                              void* d_out, int out_size) {
    const float* x   = (const float*)d_in[0];
    const float* tc  = (const float*)d_in[1];
    const float* aw  = (const float*)d_in[2];
    const float* ab  = (const float*)d_in[3];
    const float* gw  = (const float*)d_in[4];
    const float* w1  = (const float*)d_in[5];
    const float* b1  = (const float*)d_in[6];
    const float* w2  = (const float*)d_in[7];
    const float* b2  = (const float*)d_in[8];
    const float* sw1 = (const float*)d_in[9];
    const float* sb1 = (const float*)d_in[10];
    const float* sw2 = (const float*)d_in[11];
    const float* sb2 = (const float*)d_in[12];
    float* out = (float*)d_out;

    cudaFuncSetAttribute(moe_hgemm<true >, cudaFuncAttributeMaxDynamicSharedMemorySize, SMEM_BYTES);
    cudaFuncSetAttribute(moe_hgemm<false>, cudaFuncAttributeMaxDynamicSharedMemorySize, SMEM_BYTES);

    init_kernel<<<1, 32>>>();
    cond_kernel<<<dim3((2 * DIM) / 256, NBATCH), 256>>>(tc, aw, ab);
    adaln_route<<<TKN, 256>>>(x, gw);

    // fp32 -> fp16 weight conversion into scratch
    void* p;
    cudaGetSymbolAddress(&p, g_w1h);  uint2* w1h = (uint2*)p;
    cudaGetSymbolAddress(&p, g_w2h);  uint2* w2h = (uint2*)p;
    cudaGetSymbolAddress(&p, g_sw1h); uint2* s1h = (uint2*)p;
    cudaGetSymbolAddress(&p, g_sw2h); uint2* s2h = (uint2*)p;
    {
        int n4a = NEXP * DIM * HID / 4;
        int n4s = DIM * HID / 4;
        f2h_kernel<<<(n4a + 255) / 256, 256>>>((const float4*)w1,  w1h, n4a);
        f2h_kernel<<<(n4a + 255) / 256, 256>>>((const float4*)w2,  w2h, n4a);
        f2h_kernel<<<(n4s + 255) / 256, 256>>>((const float4*)sw1, s1h, n4s);
        f2h_kernel<<<(n4s + 255) / 256, 256>>>((const float4*)sw2, s2h, n4s);
    }

    moe_hgemm<true ><<<dim3(HID / BN, TKN / BM, 9), 256, SMEM_BYTES>>>(
        (const __half*)w1h, (const __half*)s1h, b1, sb1);
    moe_hgemm<false><<<dim3(DIM / BN, TKN / BM, 9), 256, SMEM_BYTES>>>(
        (const __half*)w2h, (const __half*)s2h, b2, sb2);
    combine_kernel<<<TKN, 256>>>(x, out);
}

// round 7
// speedup vs baseline: 1.7261x; 1.2322x over previous
#include <cuda_runtime.h>
#include <cuda_fp16.h>
#include <cstdint>
#include <cstddef>

// ---------------------------------------------------------------------------
// GlobalFeatureMoE: AdaLN + top-2 MoE (8 routed + 1 shared expert) + residual
// fp16 mma.sync.m16n8k16 (fp32 accum), 128x128 tiles, 2 CTAs/SM, cp.async x4
// ---------------------------------------------------------------------------

constexpr int TKN  = 8192;   // B*L
constexpr int DIM  = 1024;
constexpr int NEXP = 8;
constexpr int HID  = 4096;
constexpr int NBATCH = 4;
constexpr int SEQ  = 2048;

constexpr int BM = 128, BN = 128, BK = 32, NSTAGE = 4;
constexpr int STAGE = 16384;               // A 8KB (2 x 4KB k16-halves) + B 8KB
constexpr int SMEM_BYTES = NSTAGE * STAGE; // 65536 -> 2 CTAs/SM

// scratch (static __device__ arrays — allocation-free per harness rules)
__device__ float  g_cond[NBATCH * 2 * DIM];
__device__ int    g_cnt[NEXP];
__device__ int    g_idx[NEXP * TKN];
__device__ int    g_re[2 * TKN];
__device__ int    g_rs[2 * TKN];
__device__ float  g_rw[2 * TKN];
__device__ __half g_xnh[(size_t)TKN * DIM];          // fp16 normalized tokens
__device__ __half g_hf [(size_t)9 * TKN * HID];      // fp16 hidden per bucket
__device__ float  g_o2 [(size_t)9 * TKN * DIM];      // fp32 expert outputs
__device__ __half g_w1h[(size_t)NEXP * DIM * HID];
__device__ __half g_w2h[(size_t)NEXP * HID * DIM];
__device__ __half g_sw1h[(size_t)DIM * HID];
__device__ __half g_sw2h[(size_t)HID * DIM];

// ---------------------------------------------------------------------------
__device__ __forceinline__ uint32_t smem_u32(const void* p) {
    uint32_t a;
    asm("{ .reg .u64 t; cvta.to.shared.u64 t, %1; cvt.u32.u64 %0, t; }" : "=r"(a) : "l"(p));
    return a;
}
#define CP_ASYNC16(dst, src) \
    asm volatile("cp.async.cg.shared.global [%0], [%1], 16;" :: "r"(dst), "l"(src))
#define CP_COMMIT() asm volatile("cp.async.commit_group;" ::: "memory")
#define CP_WAIT(n)  asm volatile("cp.async.wait_group %0;" :: "n"(n) : "memory")

#define LDSM_X4(r, addr) \
    asm volatile("ldmatrix.sync.aligned.m8n8.x4.shared.b16 {%0,%1,%2,%3}, [%4];" \
        : "=r"((r)[0]), "=r"((r)[1]), "=r"((r)[2]), "=r"((r)[3]) : "r"(addr))
#define LDSM_X4T(r, addr) \
    asm volatile("ldmatrix.sync.aligned.m8n8.x4.trans.shared.b16 {%0,%1,%2,%3}, [%4];" \
        : "=r"((r)[0]), "=r"((r)[1]), "=r"((r)[2]), "=r"((r)[3]) : "r"(addr))

__device__ __forceinline__ void mma_f16(float* c, const uint32_t* a, const uint32_t* b) {
    asm volatile(
        "mma.sync.aligned.m16n8k16.row.col.f32.f16.f16.f32 "
        "{%0,%1,%2,%3}, {%4,%5,%6,%7}, {%8,%9}, {%0,%1,%2,%3};\n"
        : "+f"(c[0]), "+f"(c[1]), "+f"(c[2]), "+f"(c[3])
        : "r"(a[0]), "r"(a[1]), "r"(a[2]), "r"(a[3]), "r"(b[0]), "r"(b[1]));
}

__device__ __forceinline__ float gelu_t(float v) {
    float u = 0.7978845608028654f * (v + 0.044715f * v * v * v);
    return 0.5f * v * (1.0f + tanhf(u));
}

// ---------------------------------------------------------------------------
__global__ void init_kernel() {
    if (threadIdx.x < NEXP) g_cnt[threadIdx.x] = 0;
}

// single-launch fp32 -> fp16 conversion of all four weight matrices
__global__ void f2h_all(const float4* __restrict__ w1, const float4* __restrict__ w2,
                        const float4* __restrict__ s1, const float4* __restrict__ s2,
                        uint2* __restrict__ o1, uint2* __restrict__ o2,
                        uint2* __restrict__ o3, uint2* __restrict__ o4) {
    constexpr long N1 = (long)NEXP * DIM * HID / 4;   // 8388608
    constexpr long NS = (long)DIM * HID / 4;          // 1048576
    long i = (long)blockIdx.x * blockDim.x + threadIdx.x;
    const float4* in; uint2* out; long j;
    if      (i < N1)           { in = w1; out = o1; j = i; }
    else if (i < 2 * N1)       { in = w2; out = o2; j = i - N1; }
    else if (i < 2 * N1 + NS)  { in = s1; out = o3; j = i - 2 * N1; }
    else if (i < 2 * N1 + 2*NS){ in = s2; out = o4; j = i - 2 * N1 - NS; }
    else return;
    float4 v = in[j];
    __half2 a = __floats2half2_rn(v.x, v.y);
    __half2 b = __floats2half2_rn(v.z, v.w);
    out[j] = make_uint2(*(uint32_t*)&a, *(uint32_t*)&b);
}

// cond = silu(time_c) @ ada_w + ada_b
__global__ void cond_kernel(const float* __restrict__ tc,
                            const float* __restrict__ aw,
                            const float* __restrict__ ab) {
    __shared__ float s[DIM];
    int b = blockIdx.y;
    for (int i = threadIdx.x; i < DIM; i += blockDim.x) {
        float v = tc[(size_t)b * DIM + i];
        s[i] = v / (1.0f + expf(-v));
    }
    __syncthreads();
    int col = blockIdx.x * blockDim.x + threadIdx.x;
    float acc = ab[col];
    #pragma unroll 8
    for (int k = 0; k < DIM; ++k)
        acc += s[k] * aw[(size_t)k * (2 * DIM) + col];
    g_cond[(size_t)b * (2 * DIM) + col] = acc;
}

// fused AdaLN + fp32 gate + top-2 routing; writes fp16 xn
__global__ void adaln_route(const float* __restrict__ x,
                            const float* __restrict__ gw) {
    int t   = blockIdx.x;
    int tid = threadIdx.x;
    int lane = tid & 31, wid = tid >> 5;
    int b = t / SEQ;

    float4 xv = reinterpret_cast<const float4*>(x + (size_t)t * DIM)[tid];
    float s  = xv.x + xv.y + xv.z + xv.w;
    float ss = xv.x*xv.x + xv.y*xv.y + xv.z*xv.z + xv.w*xv.w;
    #pragma unroll
    for (int o = 16; o > 0; o >>= 1) {
        s  += __shfl_down_sync(0xffffffffu, s,  o);
        ss += __shfl_down_sync(0xffffffffu, ss, o);
    }
    __shared__ float red[2][8];
    if (lane == 0) { red[0][wid] = s; red[1][wid] = ss; }
    __syncthreads();
    float mu = 0.f, m2 = 0.f;
    #pragma unroll
    for (int w = 0; w < 8; ++w) { mu += red[0][w]; m2 += red[1][w]; }
    mu *= (1.0f / DIM); m2 *= (1.0f / DIM);
    float rstd = rsqrtf(m2 - mu * mu + 1e-6f);

    float4 sh = reinterpret_cast<const float4*>(g_cond + (size_t)b*2*DIM)[tid];
    float4 sc = reinterpret_cast<const float4*>(g_cond + (size_t)b*2*DIM + DIM)[tid];
    float4 xn;
    xn.x = (xv.x - mu) * rstd * (1.0f + sc.x) + sh.x;
    xn.y = (xv.y - mu) * rstd * (1.0f + sc.y) + sh.y;
    xn.z = (xv.z - mu) * rstd * (1.0f + sc.z) + sh.z;
    xn.w = (xv.w - mu) * rstd * (1.0f + sc.w) + sh.w;
    {
        __half2 h01 = __floats2half2_rn(xn.x, xn.y);
        __half2 h23 = __floats2half2_rn(xn.z, xn.w);
        *(uint2*)(g_xnh + (size_t)t * DIM + tid * 4) =
            make_uint2(*(uint32_t*)&h01, *(uint32_t*)&h23);
    }

    // gate logits in exact fp32
    float l[8];
    #pragma unroll
    for (int e = 0; e < 8; ++e) l[e] = 0.f;
    int d = tid * 4;
    float xs[4] = {xn.x, xn.y, xn.z, xn.w};
    #pragma unroll
    for (int j = 0; j < 4; ++j) {
        const float* wr = gw + (size_t)(d + j) * NEXP;
        #pragma unroll
        for (int e = 0; e < 8; ++e) l[e] += xs[j] * wr[e];
    }
    #pragma unroll
    for (int e = 0; e < 8; ++e) {
        #pragma unroll
        for (int o = 16; o > 0; o >>= 1)
            l[e] += __shfl_down_sync(0xffffffffu, l[e], o);
    }
    __shared__ float lred[8][8];
    if (lane == 0) {
        #pragma unroll
        for (int e = 0; e < 8; ++e) lred[e][wid] = l[e];
    }
    __syncthreads();
    if (tid == 0) {
        float L[8];
        #pragma unroll
        for (int e = 0; e < 8; ++e) {
            float a = 0.f;
            for (int w = 0; w < 8; ++w) a += lred[e][w];
            L[e] = a;
        }
        float mx = L[0];
        for (int e = 1; e < 8; ++e) mx = fmaxf(mx, L[e]);
        float p[8];
        for (int e = 0; e < 8; ++e) p[e] = expf(L[e] - mx);
        int ia = 0; float va = p[0];
        for (int e = 1; e < 8; ++e) if (p[e] > va) { ia = e; va = p[e]; }
        int ib = -1; float vb = -1.f;
        for (int e = 0; e < 8; ++e) if (e != ia && p[e] > vb) { ib = e; vb = p[e]; }
        float inv = 1.0f / (va + vb);
        int sa = atomicAdd(&g_cnt[ia], 1);
        int sb = atomicAdd(&g_cnt[ib], 1);
        g_idx[ia * TKN + sa] = t;
        g_idx[ib * TKN + sb] = t;
        g_re[2*t]   = ia; g_rs[2*t]   = sa; g_rw[2*t]   = va * inv;
        g_re[2*t+1] = ib; g_rs[2*t+1] = sb; g_rw[2*t+1] = vb * inv;
    }
}

// ---------------------------------------------------------------------------
// fp16 GEMM: CTA 128x128xBK32, 8 warps (4m x 2n) of 32x64, 4-stage cp.async,
// 2 CTAs/SM.  blockIdx.z = expert (0..7 routed, 8 = shared)
// A smem (per stage): 2 k16-halves of [128 rows][32B], granule c of row r at
//   +((c ^ ((r>>2)&1))<<4).  B smem: [32 k][256B], granule g of row k at
//   +((g ^ (k&7))<<4).
// ---------------------------------------------------------------------------
template <bool GATHER>   // true: xnh -> gelu(xW1+b1) = g_hf ; false: g_hf -> hW2+b2 = g_o2
__global__ __launch_bounds__(256, 2) void moe_hgemm(
    const __half* __restrict__ Wr, const __half* __restrict__ Ws,
    const float* __restrict__ br, const float* __restrict__ bs) {
    constexpr int NOUT = GATHER ? HID : DIM;
    constexpr int KD   = GATHER ? DIM : HID;
    constexpr int NKT  = KD / BK;

    extern __shared__ char smem[];
    const int e   = blockIdx.z;
    const int cnt = (e < NEXP) ? g_cnt[e] : TKN;
    const int m0  = blockIdx.y * BM;
    if (m0 >= cnt) return;
    const int n0  = blockIdx.x * BN;
    const __half* W    = (e < NEXP) ? Wr + (size_t)e * KD * NOUT : Ws;
    const float*  bias = (e < NEXP) ? br + (size_t)e * NOUT      : bs;
    const __half* Ah   = GATHER ? g_xnh : g_hf;

    const uint32_t sbase = smem_u32(smem);
    const int tid = threadIdx.x, lane = tid & 31, wid = tid >> 5;
    const int wm = wid >> 1, wn = wid & 1;

    // ---- staging: A row tid&127 (half tid>>7, 2 granules), B 2 granules
    const int arow = tid & 127, ahalf = tid >> 7;
    int gr_s = m0 + arow;
    long aidx;
    if (GATHER) aidx = (e < NEXP) ? ((gr_s < cnt) ? g_idx[e * TKN + gr_s] : 0) : gr_s;
    else        aidx = (long)e * TKN + gr_s;
    const char* aRow = (const char*)(Ah + (size_t)aidx * KD) + ahalf * 32;
    uint32_t aOff[2];
    #pragma unroll
    for (int c = 0; c < 2; ++c)
        aOff[c] = (uint32_t)(ahalf * 4096 + arow * 32 + ((c ^ ((arow >> 2) & 1)) << 4));
    const int bk0 = tid >> 3;                 // 0..31
    const int gn0 = (tid & 7) * 2;            // even granule 0..14
    const char* bRow = (const char*)(W + (size_t)bk0 * NOUT + n0 + gn0 * 8);
    uint32_t bOff[2];
    #pragma unroll
    for (int c = 0; c < 2; ++c)
        bOff[c] = (uint32_t)(8192 + bk0 * 256 + (((gn0 + c) ^ (bk0 & 7)) << 4));
    const size_t bStride = (size_t)BK * NOUT * sizeof(__half);

    auto load_stage = [&](int kt) {
        uint32_t so = sbase + (uint32_t)((kt & (NSTAGE - 1)) * STAGE);
        const char* as = aRow + (size_t)kt * (BK * 2);
        CP_ASYNC16(so + aOff[0], as);
        CP_ASYNC16(so + aOff[1], as + 16);
        const char* bsrc = bRow + (size_t)kt * bStride;
        CP_ASYNC16(so + bOff[0], bsrc);
        CP_ASYNC16(so + bOff[1], bsrc + 16);
        CP_COMMIT();
    };

    // ---- fragment addresses (stage-relative)
    const int rr = lane & 15, cc = lane >> 4;
    const uint32_t aswz = (uint32_t)((cc ^ ((rr >> 2) & 1)) << 4);
    uint32_t aAddr[2];
    #pragma unroll
    for (int mi = 0; mi < 2; ++mi)
        aAddr[mi] = (uint32_t)((wm * 32 + mi * 16 + rr) * 32) + aswz;
    const int kk = ((lane >> 3) & 1) * 8 + (lane & 7);
    const int j2 = lane >> 4;
    uint32_t bAddr[4];
    #pragma unroll
    for (int p = 0; p < 4; ++p)
        bAddr[p] = (uint32_t)(8192 + kk * 256 + (((wn * 8 + p * 2 + j2) ^ (lane & 7)) << 4));

    float acc[2][8][4];
    #pragma unroll
    for (int mi = 0; mi < 2; ++mi)
        #pragma unroll
        for (int ni = 0; ni < 8; ++ni)
            #pragma unroll
            for (int q = 0; q < 4; ++q) acc[mi][ni][q] = 0.f;

    load_stage(0); load_stage(1); load_stage(2);

    for (int kt = 0; kt < NKT; ++kt) {
        CP_WAIT(2);
        __syncthreads();
        if (kt + 3 < NKT) load_stage(kt + 3); else CP_COMMIT();

        const uint32_t sA = sbase + (uint32_t)((kt & (NSTAGE - 1)) * STAGE);
        #pragma unroll
        for (int s2 = 0; s2 < 2; ++s2) {
            uint32_t a[2][4], b[8][2];
            #pragma unroll
            for (int mi = 0; mi < 2; ++mi)
                LDSM_X4(a[mi], sA + s2 * 4096 + aAddr[mi]);
            #pragma unroll
            for (int p = 0; p < 4; ++p) {
                uint32_t t4[4];
                LDSM_X4T(t4, sA + s2 * 4096 + bAddr[p]);
                b[2*p][0] = t4[0]; b[2*p][1] = t4[1];
                b[2*p+1][0] = t4[2]; b[2*p+1][1] = t4[3];
            }
            #pragma unroll
            for (int mi = 0; mi < 2; ++mi)
                #pragma unroll
                for (int ni = 0; ni < 8; ++ni)
                    mma_f16(acc[mi][ni], a[mi], b[ni]);
        }
    }

    // ---- epilogue
    const int grp = lane >> 2, qid = lane & 3;
    #pragma unroll
    for (int mi = 0; mi < 2; ++mi) {
        const int r0 = m0 + wm * 32 + mi * 16 + grp;
        #pragma unroll
        for (int ni = 0; ni < 8; ++ni) {
            const int c = n0 + wn * 64 + ni * 8 + qid * 2;
            const float2 bv = *(const float2*)(bias + c);
            float v00 = acc[mi][ni][0] + bv.x;
            float v01 = acc[mi][ni][1] + bv.y;
            float v10 = acc[mi][ni][2] + bv.x;
            float v11 = acc[mi][ni][3] + bv.y;
            if (GATHER) {
                v00 = gelu_t(v00); v01 = gelu_t(v01);
                v10 = gelu_t(v10); v11 = gelu_t(v11);
                if (r0 < cnt) {
                    __half2 h = __floats2half2_rn(v00, v01);
                    *(__half2*)(g_hf + ((size_t)e * TKN + r0) * NOUT + c) = h;
                }
                if (r0 + 8 < cnt) {
                    __half2 h = __floats2half2_rn(v10, v11);
                    *(__half2*)(g_hf + ((size_t)e * TKN + r0 + 8) * NOUT + c) = h;
                }
            } else {
                if (r0 < cnt)
                    *(float2*)(g_o2 + ((size_t)e * TKN + r0) * NOUT + c) = make_float2(v00, v01);
                if (r0 + 8 < cnt)
                    *(float2*)(g_o2 + ((size_t)e * TKN + r0 + 8) * NOUT + c) = make_float2(v10, v11);
            }
        }
    }
}

// out = x + shared + w0*routed0 + w1*routed1
__global__ void combine_kernel(const float* __restrict__ x, float* __restrict__ out) {
    int t = blockIdx.x, tid = threadIdx.x;
    int e0 = g_re[2*t],     s0 = g_rs[2*t];
    int e1 = g_re[2*t + 1], s1 = g_rs[2*t + 1];
    float w0 = g_rw[2*t], w1 = g_rw[2*t + 1];
    const float4* xp  = (const float4*)(x + (size_t)t * DIM);
    const float4* shp = (const float4*)(g_o2 + ((size_t)NEXP * TKN + t) * DIM);
    const float4* r0p = (const float4*)(g_o2 + ((size_t)e0 * TKN + s0) * DIM);
    const float4* r1p = (const float4*)(g_o2 + ((size_t)e1 * TKN + s1) * DIM);
    float4 xv = xp[tid], sv = shp[tid], a = r0p[tid], b = r1p[tid];
    float4 o;
    o.x = xv.x + sv.x + w0 * a.x + w1 * b.x;
    o.y = xv.y + sv.y + w0 * a.y + w1 * b.y;
    o.z = xv.z + sv.z + w0 * a.z + w1 * b.z;
    o.w = xv.w + sv.w + w0 * a.w + w1 * b.w;
    ((float4*)(out + (size_t)t * DIM))[tid] = o;
}

// ---------------------------------------------------------------------------
extern "C" void kernel_launch(void* const* d_in, const int* in_sizes, int n_in,
                              void* d_out, int out_size) {
    const float* x   = (const float*)d_in[0];
    const float* tc  = (const float*)d_in[1];
    const float* aw  = (const float*)d_in[2];
    const float* ab  = (const float*)d_in[3];
    const float* gw  = (const float*)d_in[4];
    const float* w1  = (const float*)d_in[5];
    const float* b1  = (const float*)d_in[6];
    const float* w2  = (const float*)d_in[7];
    const float* b2  = (const float*)d_in[8];
    const float* sw1 = (const float*)d_in[9];
    const float* sb1 = (const float*)d_in[10];
    const float* sw2 = (const float*)d_in[11];
    const float* sb2 = (const float*)d_in[12];
    float* out = (float*)d_out;

    cudaFuncSetAttribute(moe_hgemm<true >, cudaFuncAttributeMaxDynamicSharedMemorySize, SMEM_BYTES);
    cudaFuncSetAttribute(moe_hgemm<false>, cudaFuncAttributeMaxDynamicSharedMemorySize, SMEM_BYTES);

    void* p;
    cudaGetSymbolAddress(&p, g_w1h);  uint2* w1h = (uint2*)p;
    cudaGetSymbolAddress(&p, g_w2h);  uint2* w2h = (uint2*)p;
    cudaGetSymbolAddress(&p, g_sw1h); uint2* s1h = (uint2*)p;
    cudaGetSymbolAddress(&p, g_sw2h); uint2* s2h = (uint2*)p;

    init_kernel<<<1, 32>>>();                                            // #0
    cond_kernel<<<dim3((2 * DIM) / 256, NBATCH), 256>>>(tc, aw, ab);     // #1
    adaln_route<<<TKN, 256>>>(x, gw);                                    // #2
    {
        long total4 = 2L * NEXP * DIM * HID / 4 + 2L * DIM * HID / 4;
        f2h_all<<<(int)((total4 + 255) / 256), 256>>>(                   // #3
            (const float4*)w1, (const float4*)w2, (const float4*)sw1, (const float4*)sw2,
            w1h, w2h, s1h, s2h);
    }
    moe_hgemm<true ><<<dim3(HID / BN, TKN / BM, 9), 256, SMEM_BYTES>>>(  // #4
        (const __half*)w1h, (const __half*)s1h, b1, sb1);
    moe_hgemm<false><<<dim3(DIM / BN, TKN / BM, 9), 256, SMEM_BYTES>>>(  // #5 (ncu -s 5)
        (const __half*)w2h, (const __half*)s2h, b2, sb2);
    combine_kernel<<<TKN, 256>>>(x, out);                                // #6
}